// round 7
// baseline (speedup 1.0000x reference)
#include <cuda_runtime.h>
#include <math.h>

#define BB 16
#define AA 3
#define SDIM 80
#define NC 80
#define NT 32
#define SSP (SDIM * SDIM)             // 6400
#define CH (5 + NC)                   // 85
#define CELLS (BB * AA * SSP)         // 307200
#define NTHR 256
#define F4_PER_THR 4
#define CONF_BLK (CELLS / 4 / (NTHR * F4_PER_THR))   // 75
#define TOT_BLK (CONF_BLK + BB)                      // 91
#define BOUT_STRIDE 8
#define EPSF 1e-7f
#define IMG 640.0f
#define STRIDEF 8.0f

// Scratch: every word rewritten by plain stores each call. No cross-call state.
__device__ float g_confpart[CONF_BLK];
__device__ float g_batchout[BB * BOUT_STRIDE];   // per-batch: cnt,ciou,bce,sp,cls

__device__ __forceinline__ float softplusf(float x) {
    return fmaxf(x, 0.0f) + log1pf(__expf(-fabsf(x)));
}
__device__ __forceinline__ float sigmoidf(float x) {
    return 1.0f / (1.0f + __expf(-x));
}

__device__ __forceinline__ float ciou_f(
    float px1, float py1, float px2, float py2,
    float tx1, float ty1, float tx2, float ty2)
{
    float iw = fmaxf(fminf(px2, tx2) - fmaxf(px1, tx1), 0.0f);
    float ih = fmaxf(fminf(py2, ty2) - fmaxf(py1, ty1), 0.0f);
    float inter = iw * ih;
    float pa = fmaxf(px2 - px1, 0.0f) * fmaxf(py2 - py1, 0.0f);
    float ta = fmaxf(tx2 - tx1, 0.0f) * fmaxf(ty2 - ty1, 0.0f);
    float un = pa + ta - inter + EPSF;
    float iou = inter / un;
    float dx = 0.5f * (px1 + px2) - 0.5f * (tx1 + tx2);
    float dy = 0.5f * (py1 + py2) - 0.5f * (ty1 + ty2);
    float cd = dx * dx + dy * dy;
    float ew = fmaxf(px2, tx2) - fminf(px1, tx1);
    float eh = fmaxf(py2, ty2) - fminf(py1, ty1);
    float ed = ew * ew + eh * eh + EPSF;
    float pw = fmaxf(px2 - px1, EPSF);
    float ph = fmaxf(py2 - py1, EPSF);
    float tw = fmaxf(tx2 - tx1, EPSF);
    float th = fmaxf(ty2 - ty1, EPSF);
    float da = atanf(tw / th) - atanf(pw / ph);
    float v = (4.0f / ((float)M_PI * (float)M_PI)) * da * da;
    float alpha = v / (1.0f - iou + v + EPSF);
    return iou - cd / ed - alpha * v;
}

// ── Kernel A: conf partials (blocks 0..74) + per-batch obj (blocks 75..90) ──
__global__ void __launch_bounds__(NTHR)
k_work(const float* __restrict__ preds,
       const float* __restrict__ anchors,
       const int* __restrict__ tcls,
       const float* __restrict__ tbox)
{
    __shared__ float red[8];
    int tid = threadIdx.x;
    int blk = blockIdx.x;

    if (blk < CONF_BLK) {
        // conf: 4 independent float4 loads per thread (MLP=4, one round-trip)
        float s = 0.0f;
        #pragma unroll
        for (int k = 0; k < F4_PER_THR; k++) {
            int idx = blk * (NTHR * F4_PER_THR) + k * NTHR + tid;
            int plane = idx / (SSP / 4);
            int off4  = idx - plane * (SSP / 4);
            int b = plane / AA, a = plane - AA * b;
            const float4* p4 = (const float4*)(preds +
                ((size_t)(b * (AA * CH) + a * CH + 4)) * SSP);
            float4 v = p4[off4];
            s += softplusf(v.x) + softplusf(v.y) + softplusf(v.z) + softplusf(v.w);
        }
        #pragma unroll
        for (int o = 16; o > 0; o >>= 1) s += __shfl_down_sync(0xffffffffu, s, o);
        if ((tid & 31) == 0) red[tid >> 5] = s;
        __syncthreads();
        if (tid == 0) {
            float t = 0.f;
            #pragma unroll
            for (int w = 0; w < 8; w++) t += red[w];
            g_confpart[blk] = t;
        }
        return;
    }

    // ── batch block: all 32 targets of batch b ──
    __shared__ float4   s_tbox[NT];
    __shared__ int      s_cls[NT];
    __shared__ float    s_anch[2 * AA];
    __shared__ int      s_cell[NT];
    __shared__ int      s_base[NT];        // -1 for non-owners
    __shared__ unsigned s_bits[NT][3];
    __shared__ int      s_lastm[NT];
    __shared__ float    s_pred[NT][5];
    __shared__ float    s_clsacc;

    int b = blk - CONF_BLK;                // 0..15

    // round-trip 1: all small inputs in parallel
    if (tid < NT) {
        s_tbox[tid] = ((const float4*)tbox)[b * NT + tid];
        s_cls[tid]  = tcls[b * NT + tid];
    } else if (tid >= 64 && tid < 64 + 2 * AA) {
        s_anch[tid - 64] = anchors[tid - 64];
    }
    if (tid == 0) s_clsacc = 0.0f;
    __syncthreads();

    // assignments (ALU only)
    if (tid < NT) {
        float4 tb = s_tbox[tid];
        int gi = min(max((int)floorf(tb.x * (float)SDIM), 0), SDIM - 1);
        int gj = min(max((int)floorf(tb.y * (float)SDIM), 0), SDIM - 1);
        float tw = tb.z * IMG, th = tb.w * IMG;
        float best = -1.0f; int a = 0;
        #pragma unroll
        for (int k = 0; k < AA; k++) {
            float awk = s_anch[2 * k], ahk = s_anch[2 * k + 1];
            float inter = fminf(tw, awk) * fminf(th, ahk);
            float un = tw * th + awk * ahk - inter;
            float r = inter / un;
            if (r > best) { best = r; a = k; }   // first-max wins (jnp.argmax)
        }
        s_cell[tid] = ((b * AA + a) * SDIM + gj) * SDIM + gi;
    }
    __syncthreads();

    // dedup: owner = smallest m with this cell; owners gather class set + lastm
    if (tid < NT) {
        int cell = s_cell[tid];
        bool owner = true;
        for (int m = 0; m < tid; m++)
            if (s_cell[m] == cell) { owner = false; break; }
        if (owner) {
            unsigned b0 = 0u, b1 = 0u, b2 = 0u;
            int lastm = tid;
            for (int m = 0; m < NT; m++) {
                if (s_cell[m] == cell) {
                    int c = s_cls[m];
                    if (c < 32)      b0 |= 1u << c;
                    else if (c < 64) b1 |= 1u << (c - 32);
                    else             b2 |= 1u << (c - 64);
                    lastm = m;
                }
            }
            s_bits[tid][0] = b0; s_bits[tid][1] = b1; s_bits[tid][2] = b2;
            s_lastm[tid] = lastm;
            int gi = cell % SDIM;
            int gj = (cell / SDIM) % SDIM;
            int a  = (cell / SSP) % AA;
            s_base[tid] = (b * (AA * CH) + a * CH) * SSP + gj * SDIM + gi;
        } else {
            s_base[tid] = -1;
        }
    }
    __syncthreads();

    // round-trip 2: 32×80 class logits + 32×5 box/conf preds, all parallel
    float cls_acc = 0.0f;
    #pragma unroll
    for (int k = 0; k < (NT * NC) / NTHR; k++) {       // 10 iterations
        int item = k * NTHR + tid;                     // 0..2559
        int n = item / NC, c = item - n * NC;
        int base = s_base[n];
        if (base >= 0) {
            float l = preds[(size_t)base + (size_t)(5 + c) * SSP];
            float tgt = (float)((s_bits[n][c >> 5] >> (c & 31)) & 1u);
            cls_acc += softplusf(l) - l * tgt;
        }
    }
    if (tid < NT * 5) {                                // 160 pred loads
        int n = tid / 5, k2 = tid - n * 5;
        int base = s_base[n];
        if (base >= 0)
            s_pred[n][k2] = preds[(size_t)base + (size_t)k2 * SSP];
    }
    __syncthreads();

    // per-owner CIoU + conf terms (tid<32)
    float f_cnt = 0.f, f_ciou = 0.f, f_bce = 0.f, f_sp = 0.f;
    if (tid < NT && s_base[tid] >= 0) {
        int cell = s_cell[tid];
        int gi = cell % SDIM;
        int gj = (cell / SDIM) % SDIM;
        int a  = (cell / SSP) % AA;

        float4 tb = s_tbox[s_lastm[tid]];
        float cx = tb.x * IMG, cy = tb.y * IMG;
        float tw = tb.z * IMG, th = tb.w * IMG;

        float pcx = (sigmoidf(s_pred[tid][0]) + (float)gi) * STRIDEF;
        float pcy = (sigmoidf(s_pred[tid][1]) + (float)gj) * STRIDEF;
        float pw = s_anch[2 * a]     * __expf(s_pred[tid][2]);
        float ph = s_anch[2 * a + 1] * __expf(s_pred[tid][3]);
        float pc = s_pred[tid][4];

        f_ciou = ciou_f(pcx - 0.5f * pw, pcy - 0.5f * ph,
                        pcx + 0.5f * pw, pcy + 0.5f * ph,
                        cx - 0.5f * tw, cy - 0.5f * th,
                        cx + 0.5f * tw, cy + 0.5f * th);
        f_sp  = softplusf(pc);
        f_bce = f_sp - pc;
        f_cnt = 1.0f;
    }

    // reduce cls over whole block (warp shfl + shared atomic), 4 vals in warp 0
    #pragma unroll
    for (int o = 16; o > 0; o >>= 1)
        cls_acc += __shfl_down_sync(0xffffffffu, cls_acc, o);
    if ((tid & 31) == 0) atomicAdd(&s_clsacc, cls_acc);

    if (tid < 32) {
        #pragma unroll
        for (int o = 16; o > 0; o >>= 1) {
            f_cnt  += __shfl_down_sync(0xffffffffu, f_cnt,  o);
            f_ciou += __shfl_down_sync(0xffffffffu, f_ciou, o);
            f_bce  += __shfl_down_sync(0xffffffffu, f_bce,  o);
            f_sp   += __shfl_down_sync(0xffffffffu, f_sp,   o);
        }
    }
    __syncthreads();

    if (tid == 0) {
        float* slot = g_batchout + b * BOUT_STRIDE;
        slot[0] = f_cnt;
        slot[1] = f_ciou;
        slot[2] = f_bce;
        slot[3] = f_sp;
        slot[4] = s_clsacc;
    }
}

// ── Kernel B: single-warp finalize, no barriers ─────────────────────────────
__global__ void __launch_bounds__(32)
k_final(float* __restrict__ out)
{
    int tid = threadIdx.x;

    // 75 conf partials: up to 3 per lane
    float conf = 0.0f;
    #pragma unroll
    for (int k = 0; k < 3; k++) {
        int i = k * 32 + tid;
        if (i < CONF_BLK) conf += g_confpart[i];
    }

    // 16 batch slots × 5 values: lane t<16 loads batch t's slot
    float cnt = 0.f, ciou = 0.f, bce = 0.f, sp = 0.f, cls = 0.f;
    if (tid < BB) {
        const float* s = g_batchout + tid * BOUT_STRIDE;
        cnt = s[0]; ciou = s[1]; bce = s[2]; sp = s[3]; cls = s[4];
    }

    #pragma unroll
    for (int o = 16; o > 0; o >>= 1) {
        conf += __shfl_down_sync(0xffffffffu, conf, o);
        cnt  += __shfl_down_sync(0xffffffffu, cnt,  o);
        ciou += __shfl_down_sync(0xffffffffu, ciou, o);
        bce  += __shfl_down_sync(0xffffffffu, bce,  o);
        sp   += __shfl_down_sync(0xffffffffu, sp,   o);
        cls  += __shfl_down_sync(0xffffffffu, cls,  o);
    }

    if (tid == 0) {
        double nobj = (double)cnt;
        double dn_obj   = fmax(nobj, 1.0);
        double dn_noobj = fmax((double)CELLS - nobj, 1.0);
        double dn_cls   = fmax(nobj * (double)NC, 1.0);

        double loss_ciou       = 1.0 - (double)ciou / dn_obj;
        double loss_conf_obj   = (double)bce / dn_obj;
        double loss_conf_noobj = ((double)conf - (double)sp) / dn_noobj;
        double loss_cls        = (double)cls / dn_cls;

        out[0] = (float)(loss_ciou + loss_conf_obj
                         + 0.5 * loss_conf_noobj + loss_cls);
    }
}

extern "C" void kernel_launch(void* const* d_in, const int* in_sizes, int n_in,
                              void* d_out, int out_size)
{
    const float* preds   = (const float*)d_in[0];
    const float* anchors = (const float*)d_in[1];
    const int*   tcls    = (const int*)d_in[2];
    const float* tbox    = (const float*)d_in[3];

    k_work<<<TOT_BLK, NTHR>>>(preds, anchors, tcls, tbox);
    k_final<<<1, 32>>>((float*)d_out);
}

// round 8
// speedup vs baseline: 3.4016x; 3.4016x over previous
#include <cuda_runtime.h>
#include <math.h>

#define BB 16
#define AA 3
#define SDIM 80
#define NC 80
#define NT 32
#define SSP (SDIM * SDIM)             // 6400
#define CH (5 + NC)                   // 85
#define CELLS (BB * AA * SSP)         // 307200
#define NTARG (BB * NT)               // 512
#define NTHR 128
#define F4_PER_THR 4
#define CONF_BLK (CELLS / 4 / (NTHR * F4_PER_THR))   // 150
#define TOT_BLK (CONF_BLK + NTARG)                   // 662
#define EPSF 1e-7f
#define IMG 640.0f
#define STRIDEF 8.0f

__device__ __forceinline__ float softplusf(float x) {
    return fmaxf(x, 0.0f) + log1pf(__expf(-fabsf(x)));
}
__device__ __forceinline__ float sigmoidf(float x) {
    return 1.0f / (1.0f + __expf(-x));
}

// batch-local cell id from a target box (anchors in registers)
__device__ __forceinline__ int assign_cell(float4 tb, const float* anch) {
    int gi = min(max((int)floorf(tb.x * (float)SDIM), 0), SDIM - 1);
    int gj = min(max((int)floorf(tb.y * (float)SDIM), 0), SDIM - 1);
    float tw = tb.z * IMG, th = tb.w * IMG;
    float best = -1.0f; int a = 0;
    #pragma unroll
    for (int k = 0; k < AA; k++) {
        float awk = anch[2 * k], ahk = anch[2 * k + 1];
        float inter = fminf(tw, awk) * fminf(th, ahk);
        float un = tw * th + awk * ahk - inter;
        float r = inter / un;
        if (r > best) { best = r; a = k; }   // first-max wins (jnp.argmax)
    }
    return (a * SDIM + gj) * SDIM + gi;
}

// count of unique cells in 4 batches handled by this warp (same value all lanes)
__device__ __forceinline__ float warp_nobj(const float4 tb[4], const float* anch,
                                           int lane) {
    unsigned cnt = 0;
    #pragma unroll
    for (int r = 0; r < 4; r++) {
        int cell = assign_cell(tb[r], anch);
        unsigned mask = __match_any_sync(0xffffffffu, cell);
        unsigned lead = __ballot_sync(0xffffffffu, lane == (__ffs(mask) - 1));
        cnt += __popc(lead);
    }
    return (float)cnt;
}

__device__ __forceinline__ float ciou_f(
    float px1, float py1, float px2, float py2,
    float tx1, float ty1, float tx2, float ty2)
{
    float iw = fmaxf(fminf(px2, tx2) - fmaxf(px1, tx1), 0.0f);
    float ih = fmaxf(fminf(py2, ty2) - fmaxf(py1, ty1), 0.0f);
    float inter = iw * ih;
    float pa = fmaxf(px2 - px1, 0.0f) * fmaxf(py2 - py1, 0.0f);
    float ta = fmaxf(tx2 - tx1, 0.0f) * fmaxf(ty2 - ty1, 0.0f);
    float un = pa + ta - inter + EPSF;
    float iou = inter / un;
    float dx = 0.5f * (px1 + px2) - 0.5f * (tx1 + tx2);
    float dy = 0.5f * (py1 + py2) - 0.5f * (ty1 + ty2);
    float cd = dx * dx + dy * dy;
    float ew = fmaxf(px2, tx2) - fminf(px1, tx1);
    float eh = fmaxf(py2, ty2) - fminf(py1, ty1);
    float ed = ew * ew + eh * eh + EPSF;
    float pw = fmaxf(px2 - px1, EPSF);
    float ph = fmaxf(py2 - py1, EPSF);
    float tw = fmaxf(tx2 - tx1, EPSF);
    float th = fmaxf(ty2 - ty1, EPSF);
    float da = atanf(tw / th) - atanf(pw / ph);
    float v = (4.0f / ((float)M_PI * (float)M_PI)) * da * da;
    float alpha = v / (1.0f - iou + v + EPSF);
    return iou - cd / ed - alpha * v;
}

__global__ void __launch_bounds__(NTHR)
yolo_one(const float* __restrict__ preds,
         const float* __restrict__ anchors,
         const int* __restrict__ tcls,
         const float* __restrict__ tbox,
         float* __restrict__ out)
{
    int tid  = threadIdx.x;
    int lane = tid & 31;
    int w    = tid >> 5;                 // warp 0..3
    int blk  = blockIdx.x;

    // anchors → registers (uniform broadcast loads)
    float anch[2 * AA];
    #pragma unroll
    for (int k = 0; k < 2 * AA; k++) anch[k] = anchors[k];

    const float4* tbox4 = (const float4*)tbox;

    if (blk < CONF_BLK) {
        // ── conf block: 4 float4 conf loads + 4 float4 tbox loads (one RT) ──
        __shared__ float red[4];
        __shared__ float s_nobj[4];

        float4 tb[4];
        #pragma unroll
        for (int r = 0; r < 4; r++)
            tb[r] = tbox4[(w * 4 + r) * NT + lane];   // warp w covers batches 4w..4w+3

        float s = 0.0f;
        #pragma unroll
        for (int k = 0; k < F4_PER_THR; k++) {
            int idx = blk * (NTHR * F4_PER_THR) + k * NTHR + tid;
            int plane = idx / (SSP / 4);
            int off4  = idx - plane * (SSP / 4);
            int b = plane / AA, a = plane - AA * b;
            const float4* p4 = (const float4*)(preds +
                ((size_t)(b * (AA * CH) + a * CH + 4)) * SSP);
            float4 v = p4[off4];
            s += softplusf(v.x) + softplusf(v.y) + softplusf(v.z) + softplusf(v.w);
        }

        float wn = warp_nobj(tb, anch, lane);
        if (lane == 0) s_nobj[w] = wn;

        #pragma unroll
        for (int o = 16; o > 0; o >>= 1) s += __shfl_down_sync(0xffffffffu, s, o);
        if (lane == 0) red[w] = s;
        __syncthreads();

        if (tid == 0) {
            float bsum = red[0] + red[1] + red[2] + red[3];
            float nobj = s_nobj[0] + s_nobj[1] + s_nobj[2] + s_nobj[3];
            float dn_noobj = fmaxf((float)CELLS - nobj, 1.0f);
            float c = 0.5f * bsum / dn_noobj;
            if (blk == 0) c += 1.0f;             // constant term of loss_ciou
            atomicAdd(out, c);
        }
        return;
    }

    // ── obj block: one per target, R6 thin shape ──
    __shared__ float4   s_tb[NT];
    __shared__ int      s_cls[NT];
    __shared__ int      s_cell[NT];
    __shared__ unsigned s_bits[3];
    __shared__ int      s_lastm;
    __shared__ float    s_pred[5];
    __shared__ float    red[4];
    __shared__ float    s_nobj[4];

    int t = blk - CONF_BLK;                 // 0..511
    int b = t >> 5, n = t & 31;

    // RT1: batch inputs + all-batch tbox for nobj (independent loads)
    float4 tb[4];
    #pragma unroll
    for (int r = 0; r < 4; r++)
        tb[r] = tbox4[(w * 4 + r) * NT + lane];

    if (tid < NT) {
        s_tb[tid]  = tbox4[b * NT + tid];
        s_cls[tid] = tcls[b * NT + tid];
    }
    if (tid == 0) { s_bits[0] = s_bits[1] = s_bits[2] = 0u; s_lastm = -1; }
    __syncthreads();

    if (tid < NT) s_cell[tid] = assign_cell(s_tb[tid], anch);
    __syncthreads();

    int cell = s_cell[n];
    bool owner = true;                       // block-uniform
    for (int m = 0; m < n; m++)
        if (s_cell[m] == cell) { owner = false; break; }
    if (!owner) return;                      // whole block exits together

    // global nobj (cheap, register inputs)
    float wn = warp_nobj(tb, anch, lane);
    if (lane == 0) s_nobj[w] = wn;

    // class-set union + last-write-wins box index
    if (tid < NT && s_cell[tid] == cell) {
        int c = s_cls[tid];
        atomicOr(&s_bits[c >> 5], 1u << (c & 31));
        atomicMax(&s_lastm, tid);
    }

    // RT2: 80 class logits + 5 box/conf preds, all parallel
    int gi = cell % SDIM;
    int gj = (cell / SDIM) % SDIM;
    int a  = cell / SSP;
    size_t base = ((size_t)b * (AA * CH) + (size_t)a * CH) * SSP
                  + (size_t)gj * SDIM + gi;

    float l = 0.0f;
    if (tid < NC) {
        l = preds[base + (size_t)(5 + tid) * SSP];
    } else if (tid >= 96 && tid < 101) {
        s_pred[tid - 96] = preds[base + (size_t)(tid - 96) * SSP];
    }
    __syncthreads();

    float cs = 0.0f;
    if (tid < NC) {
        float tgt = (float)((s_bits[tid >> 5] >> (tid & 31)) & 1u);
        cs = softplusf(l) - l * tgt;
    }
    #pragma unroll
    for (int o = 16; o > 0; o >>= 1) cs += __shfl_down_sync(0xffffffffu, cs, o);
    if (lane == 0) red[w] = cs;
    __syncthreads();

    if (tid == 0) {
        float cls_sum = red[0] + red[1] + red[2] + red[3];
        float nobj = s_nobj[0] + s_nobj[1] + s_nobj[2] + s_nobj[3];
        float dn_obj   = fmaxf(nobj, 1.0f);
        float dn_noobj = fmaxf((float)CELLS - nobj, 1.0f);
        float dn_cls   = fmaxf(nobj * (float)NC, 1.0f);

        float4 tbx = s_tb[s_lastm];
        float cx = tbx.x * IMG, cy = tbx.y * IMG;
        float tw = tbx.z * IMG, th = tbx.w * IMG;

        float pcx = (sigmoidf(s_pred[0]) + (float)gi) * STRIDEF;
        float pcy = (sigmoidf(s_pred[1]) + (float)gj) * STRIDEF;
        float pw = anch[2 * a]     * __expf(s_pred[2]);
        float ph = anch[2 * a + 1] * __expf(s_pred[3]);
        float pc = s_pred[4];

        float ciou = ciou_f(pcx - 0.5f * pw, pcy - 0.5f * ph,
                            pcx + 0.5f * pw, pcy + 0.5f * ph,
                            cx - 0.5f * tw, cy - 0.5f * th,
                            cx + 0.5f * tw, cy + 0.5f * th);
        float sp  = softplusf(pc);
        float bce = sp - pc;

        // block's total contribution to the scalar loss
        float c = (bce - ciou) / dn_obj
                + cls_sum / dn_cls
                - 0.5f * sp / dn_noobj;
        atomicAdd(out, c);
    }
}

extern "C" void kernel_launch(void* const* d_in, const int* in_sizes, int n_in,
                              void* d_out, int out_size)
{
    const float* preds   = (const float*)d_in[0];
    const float* anchors = (const float*)d_in[1];
    const int*   tcls    = (const int*)d_in[2];
    const float* tbox    = (const float*)d_in[3];

    cudaMemsetAsync(d_out, 0, sizeof(float));    // graph-capturable memset node
    yolo_one<<<TOT_BLK, NTHR>>>(preds, anchors, tcls, tbox, (float*)d_out);
}

// round 9
// speedup vs baseline: 3.4468x; 1.0133x over previous
#include <cuda_runtime.h>
#include <math.h>

#define BB 16
#define AA 3
#define SDIM 80
#define NC 80
#define NT 32
#define SSP (SDIM * SDIM)             // 6400
#define CH (5 + NC)                   // 85
#define CELLS (BB * AA * SSP)         // 307200
#define NTARG (BB * NT)               // 512 = grid size
#define NTHR 128
#define F4_TOTAL (CELLS / 4)          // 76800
#define F4_PER_BLK (F4_TOTAL / NTARG) // 150
#define EPSF 1e-7f
#define IMG 640.0f
#define STRIDEF 8.0f

// softplus with fast log: arg of __logf is in [1,2] (max rel err ~2^-21)
__device__ __forceinline__ float softplusf(float x) {
    return fmaxf(x, 0.0f) + __logf(1.0f + __expf(-fabsf(x)));
}
__device__ __forceinline__ float sigmoidf(float x) {
    return 1.0f / (1.0f + __expf(-x));
}

// batch-local cell id from a target box (anchors in registers)
__device__ __forceinline__ int assign_cell(float4 tb, const float* anch) {
    int gi = min(max((int)floorf(tb.x * (float)SDIM), 0), SDIM - 1);
    int gj = min(max((int)floorf(tb.y * (float)SDIM), 0), SDIM - 1);
    float tw = tb.z * IMG, th = tb.w * IMG;
    float best = -1.0f; int a = 0;
    #pragma unroll
    for (int k = 0; k < AA; k++) {
        float awk = anch[2 * k], ahk = anch[2 * k + 1];
        float inter = fminf(tw, awk) * fminf(th, ahk);
        float un = tw * th + awk * ahk - inter;
        float r = inter / un;
        if (r > best) { best = r; a = k; }   // first-max wins (jnp.argmax)
    }
    return (a * SDIM + gj) * SDIM + gi;
}

// unique-cell count across 4 batches handled by this warp (uniform over warp)
__device__ __forceinline__ float warp_nobj(const float4 tb[4], const float* anch,
                                           int lane) {
    unsigned cnt = 0;
    #pragma unroll
    for (int r = 0; r < 4; r++) {
        int cell = assign_cell(tb[r], anch);
        unsigned mask = __match_any_sync(0xffffffffu, cell);
        unsigned lead = __ballot_sync(0xffffffffu, lane == (__ffs(mask) - 1));
        cnt += __popc(lead);
    }
    return (float)cnt;
}

__device__ __forceinline__ float ciou_f(
    float px1, float py1, float px2, float py2,
    float tx1, float ty1, float tx2, float ty2)
{
    float iw = fmaxf(fminf(px2, tx2) - fmaxf(px1, tx1), 0.0f);
    float ih = fmaxf(fminf(py2, ty2) - fmaxf(py1, ty1), 0.0f);
    float inter = iw * ih;
    float pa = fmaxf(px2 - px1, 0.0f) * fmaxf(py2 - py1, 0.0f);
    float ta = fmaxf(tx2 - tx1, 0.0f) * fmaxf(ty2 - ty1, 0.0f);
    float un = pa + ta - inter + EPSF;
    float iou = inter / un;
    float dx = 0.5f * (px1 + px2) - 0.5f * (tx1 + tx2);
    float dy = 0.5f * (py1 + py2) - 0.5f * (ty1 + ty2);
    float cd = dx * dx + dy * dy;
    float ew = fmaxf(px2, tx2) - fminf(px1, tx1);
    float eh = fmaxf(py2, ty2) - fminf(py1, ty1);
    float ed = ew * ew + eh * eh + EPSF;
    float pw = fmaxf(px2 - px1, EPSF);
    float ph = fmaxf(py2 - py1, EPSF);
    float tw = fmaxf(tx2 - tx1, EPSF);
    float th = fmaxf(ty2 - ty1, EPSF);
    float da = atanf(tw / th) - atanf(pw / ph);
    float v = (4.0f / ((float)M_PI * (float)M_PI)) * da * da;
    float alpha = v / (1.0f - iou + v + EPSF);
    return iou - cd / ed - alpha * v;
}

__global__ void __launch_bounds__(NTHR)
yolo_one(const float* __restrict__ preds,
         const float* __restrict__ anchors,
         const int* __restrict__ tcls,
         const float* __restrict__ tbox,
         float* __restrict__ out)
{
    __shared__ float4   s_tb[NT];
    __shared__ int      s_cls[NT];
    __shared__ int      s_cell[NT];
    __shared__ unsigned s_bits[3];
    __shared__ int      s_lastm;
    __shared__ float    s_pred[5];
    __shared__ float    red_conf[4];
    __shared__ float    red_cls[4];
    __shared__ float    s_nobj[4];

    int tid  = threadIdx.x;
    int lane = tid & 31;
    int w    = tid >> 5;
    int blk  = blockIdx.x;                // 0..511, one target per block
    int b = blk >> 5, n = blk & 31;

    float anch[2 * AA];
    #pragma unroll
    for (int k = 0; k < 2 * AA; k++) anch[k] = anchors[k];

    const float4* tbox4 = (const float4*)tbox;

    // ── RT1: conf chunk + all-batch tbox (nobj) + own-batch inputs, parallel ──
    float4 tb[4];
    #pragma unroll
    for (int r = 0; r < 4; r++)
        tb[r] = tbox4[(w * 4 + r) * NT + lane];   // warp w: batches 4w..4w+3

    if (tid < NT) {
        s_tb[tid]  = tbox4[b * NT + tid];
        s_cls[tid] = tcls[b * NT + tid];
    }
    if (tid == 0) { s_bits[0] = s_bits[1] = s_bits[2] = 0u; s_lastm = -1; }

    // conf: 150 float4 per block (~1.2 per thread), coalesced
    float s = 0.0f;
    #pragma unroll
    for (int k = 0; k < 2; k++) {
        int i = k * NTHR + tid;
        if (i < F4_PER_BLK) {
            int idx = blk * F4_PER_BLK + i;
            int plane = idx / (SSP / 4);
            int off4  = idx - plane * (SSP / 4);
            int bb = plane / AA, aa_ = plane - AA * bb;
            const float4* p4 = (const float4*)(preds +
                ((size_t)(bb * (AA * CH) + aa_ * CH + 4)) * SSP);
            float4 v = p4[off4];
            s += softplusf(v.x) + softplusf(v.y) + softplusf(v.z) + softplusf(v.w);
        }
    }
    __syncthreads();

    // assignments for own batch (ALU)
    if (tid < NT) s_cell[tid] = assign_cell(s_tb[tid], anch);
    __syncthreads();

    int cell = s_cell[n];
    bool owner = true;                      // block-uniform
    for (int m = 0; m < n; m++)
        if (s_cell[m] == cell) { owner = false; break; }

    // global nobj from registers (uniform per warp)
    float wn = warp_nobj(tb, anch, lane);
    if (lane == 0) s_nobj[w] = wn;

    // ── RT2 (owners only; block-uniform branch): 85 scattered pred loads ──
    int gi = cell % SDIM;
    int gj = (cell / SDIM) % SDIM;
    int a  = cell / SSP;
    float l = 0.0f;
    if (owner) {
        if (tid < NT && s_cell[tid] == cell) {
            int c = s_cls[tid];
            atomicOr(&s_bits[c >> 5], 1u << (c & 31));
            atomicMax(&s_lastm, tid);
        }
        size_t base = ((size_t)b * (AA * CH) + (size_t)a * CH) * SSP
                      + (size_t)gj * SDIM + gi;
        if (tid < NC) {
            l = preds[base + (size_t)(5 + tid) * SSP];
        } else if (tid >= 96 && tid < 101) {
            s_pred[tid - 96] = preds[base + (size_t)(tid - 96) * SSP];
        }
    }
    __syncthreads();

    float cs = 0.0f;
    if (owner && tid < NC) {
        float tgt = (float)((s_bits[tid >> 5] >> (tid & 31)) & 1u);
        cs = softplusf(l) - l * tgt;
    }

    // reductions: conf partial + cls, per-warp shfl into shared
    #pragma unroll
    for (int o = 16; o > 0; o >>= 1) {
        s  += __shfl_down_sync(0xffffffffu, s,  o);
        cs += __shfl_down_sync(0xffffffffu, cs, o);
    }
    if (lane == 0) { red_conf[w] = s; red_cls[w] = cs; }
    __syncthreads();

    if (tid == 0) {
        float conf_sum = red_conf[0] + red_conf[1] + red_conf[2] + red_conf[3];
        float nobj = s_nobj[0] + s_nobj[1] + s_nobj[2] + s_nobj[3];
        float dn_obj   = fmaxf(nobj, 1.0f);
        float dn_noobj = fmaxf((float)CELLS - nobj, 1.0f);
        float dn_cls   = fmaxf(nobj * (float)NC, 1.0f);

        float c = 0.5f * conf_sum / dn_noobj;
        if (blk == 0) c += 1.0f;            // constant term of loss_ciou

        if (owner) {
            float cls_sum = red_cls[0] + red_cls[1] + red_cls[2] + red_cls[3];

            float4 tbx = s_tb[s_lastm];
            float cx = tbx.x * IMG, cy = tbx.y * IMG;
            float tw = tbx.z * IMG, th = tbx.w * IMG;

            float pcx = (sigmoidf(s_pred[0]) + (float)gi) * STRIDEF;
            float pcy = (sigmoidf(s_pred[1]) + (float)gj) * STRIDEF;
            float pw = anch[2 * a]     * __expf(s_pred[2]);
            float ph = anch[2 * a + 1] * __expf(s_pred[3]);
            float pc = s_pred[4];

            float ciou = ciou_f(pcx - 0.5f * pw, pcy - 0.5f * ph,
                                pcx + 0.5f * pw, pcy + 0.5f * ph,
                                cx - 0.5f * tw, cy - 0.5f * th,
                                cx + 0.5f * tw, cy + 0.5f * th);
            float sp  = softplusf(pc);
            float bce = sp - pc;

            c += (bce - ciou) / dn_obj
               + cls_sum / dn_cls
               - 0.5f * sp / dn_noobj;
        }
        atomicAdd(out, c);
    }
}

extern "C" void kernel_launch(void* const* d_in, const int* in_sizes, int n_in,
                              void* d_out, int out_size)
{
    const float* preds   = (const float*)d_in[0];
    const float* anchors = (const float*)d_in[1];
    const int*   tcls    = (const int*)d_in[2];
    const float* tbox    = (const float*)d_in[3];

    cudaMemsetAsync(d_out, 0, sizeof(float));
    yolo_one<<<NTARG, NTHR>>>(preds, anchors, tcls, tbox, (float*)d_out);
}

// round 11
// speedup vs baseline: 4.0248x; 1.1677x over previous
#include <cuda_runtime.h>
#include <math.h>

#define BB 16
#define AA 3
#define SDIM 80
#define NC 80
#define NT 32
#define SSP (SDIM * SDIM)             // 6400
#define CH (5 + NC)                   // 85
#define CELLS (BB * AA * SSP)         // 307200
#define NTARG (BB * NT)               // 512 = grid size
#define NTHR 128
#define F4_TOTAL (CELLS / 4)          // 76800
#define F4_PER_BLK (F4_TOTAL / NTARG) // 150
#define EPSF 1e-7f
#define IMG 640.0f
#define STRIDEF 8.0f

__device__ __forceinline__ float softplusf(float x) {
    return fmaxf(x, 0.0f) + __logf(1.0f + __expf(-fabsf(x)));   // arg in [1,2]
}
__device__ __forceinline__ float sigmoidf(float x) {
    return 1.0f / (1.0f + __expf(-x));
}

__device__ __forceinline__ int assign_cell(float4 tb, const float* anch) {
    int gi = min(max((int)floorf(tb.x * (float)SDIM), 0), SDIM - 1);
    int gj = min(max((int)floorf(tb.y * (float)SDIM), 0), SDIM - 1);
    float tw = tb.z * IMG, th = tb.w * IMG;
    float best = -1.0f; int a = 0;
    #pragma unroll
    for (int k = 0; k < AA; k++) {
        float awk = anch[2 * k], ahk = anch[2 * k + 1];
        float inter = fminf(tw, awk) * fminf(th, ahk);
        float un = tw * th + awk * ahk - inter;
        float r = inter / un;
        if (r > best) { best = r; a = k; }   // first-max wins (jnp.argmax)
    }
    return (a * SDIM + gj) * SDIM + gi;
}

__device__ __forceinline__ float ciou_f(
    float px1, float py1, float px2, float py2,
    float tx1, float ty1, float tx2, float ty2)
{
    float iw = fmaxf(fminf(px2, tx2) - fmaxf(px1, tx1), 0.0f);
    float ih = fmaxf(fminf(py2, ty2) - fmaxf(py1, ty1), 0.0f);
    float inter = iw * ih;
    float pa = fmaxf(px2 - px1, 0.0f) * fmaxf(py2 - py1, 0.0f);
    float ta = fmaxf(tx2 - tx1, 0.0f) * fmaxf(ty2 - ty1, 0.0f);
    float un = pa + ta - inter + EPSF;
    float iou = inter / un;
    float dx = 0.5f * (px1 + px2) - 0.5f * (tx1 + tx2);
    float dy = 0.5f * (py1 + py2) - 0.5f * (ty1 + ty2);
    float cd = dx * dx + dy * dy;
    float ew = fmaxf(px2, tx2) - fminf(px1, tx1);
    float eh = fmaxf(py2, ty2) - fminf(py1, ty1);
    float ed = ew * ew + eh * eh + EPSF;
    float pw = fmaxf(px2 - px1, EPSF);
    float ph = fmaxf(py2 - py1, EPSF);
    float tw = fmaxf(tx2 - tx1, EPSF);
    float th = fmaxf(ty2 - ty1, EPSF);
    float da = atanf(tw / th) - atanf(pw / ph);
    float v = (4.0f / ((float)M_PI * (float)M_PI)) * da * da;
    float alpha = v / (1.0f - iou + v + EPSF);
    return iou - cd / ed - alpha * v;
}

__global__ void __launch_bounds__(NTHR)
yolo_one(const float* __restrict__ preds,
         const float* __restrict__ anchors,
         const int* __restrict__ tcls,
         const float* __restrict__ tbox,
         float* __restrict__ out)
{
    __shared__ int      s_cell;
    __shared__ int      s_owner;
    __shared__ unsigned s_bits[3];
    __shared__ float4   s_tbx;
    __shared__ float    s_pred[5];
    __shared__ float    red_conf[4];
    __shared__ float    red_cls[4];
    __shared__ float    s_nobj[4];

    int tid  = threadIdx.x;
    int lane = tid & 31;
    int w    = tid >> 5;
    int blk  = blockIdx.x;                 // one target per block
    int b = blk >> 5, n = blk & 31;
    int w_own = b >> 2, r_own = b & 3;     // warp/slot holding batch b

    float anch[2 * AA];
    #pragma unroll
    for (int k = 0; k < 2 * AA; k++) anch[k] = anchors[k];

    const float4* tbox4 = (const float4*)tbox;

    // ── RT1 (independent loads): 4 batches of tbox per warp + own-batch tcls
    //    + this block's conf chunk ──
    float4 tb[4];
    #pragma unroll
    for (int r = 0; r < 4; r++)
        tb[r] = tbox4[(w * 4 + r) * NT + lane];   // warp w: batches 4w..4w+3
    int myc = tcls[b * NT + lane];

    float s = 0.0f;
    #pragma unroll
    for (int k = 0; k < 2; k++) {
        int i = k * NTHR + tid;
        if (i < F4_PER_BLK) {
            int idx = blk * F4_PER_BLK + i;
            int plane = idx / (SSP / 4);
            int off4  = idx - plane * (SSP / 4);
            int bb = plane / AA, aa_ = plane - AA * bb;
            const float4* p4 = (const float4*)(preds +
                ((size_t)(bb * (AA * CH) + aa_ * CH + 4)) * SSP);
            float4 v = p4[off4];
            s += softplusf(v.x) + softplusf(v.y) + softplusf(v.z) + softplusf(v.w);
        }
    }

    // ── per-warp global-nobj (registers) + owner-warp dedup (collectives
    //    executed UNCONDITIONALLY by all 32 lanes of the participating warp) ──
    unsigned cnt = 0;
    #pragma unroll
    for (int r = 0; r < 4; r++) {
        int cell_r = assign_cell(tb[r], anch);
        unsigned M = __match_any_sync(0xffffffffu, cell_r);
        unsigned lead = __ballot_sync(0xffffffffu, lane == (__ffs(M) - 1));
        cnt += __popc(lead);

        if (w == w_own && r == r_own) {    // warp-uniform condition
            // all collectives below: full warp, unconditional
            unsigned Mn  = __shfl_sync(0xffffffffu, M, n);       // group of target n
            int     celln = __shfl_sync(0xffffffffu, cell_r, n);
            int     lastm = 31 - __clz(Mn);                       // last-write-wins
            float bx = __shfl_sync(0xffffffffu, tb[r].x, lastm);
            float by = __shfl_sync(0xffffffffu, tb[r].y, lastm);
            float bz = __shfl_sync(0xffffffffu, tb[r].z, lastm);
            float bw = __shfl_sync(0xffffffffu, tb[r].w, lastm);

            // class-set union: only owner warp touches s_bits before barrier 1
            if (lane < 3) s_bits[lane] = 0u;
            __syncwarp();
            if ((Mn >> lane) & 1u)
                atomicOr(&s_bits[myc >> 5], 1u << (myc & 31));

            if (lane == 0) {
                s_cell  = celln;
                s_owner = ((int)__ffs(Mn) - 1 == n);
                s_tbx   = make_float4(bx, by, bz, bw);
            }
        }
    }
    if (lane == 0) s_nobj[w] = (float)cnt;
    __syncthreads();                       // barrier 1

    int  cell  = s_cell;
    bool owner = (s_owner != 0);
    int gi = cell % SDIM;
    int gj = (cell / SDIM) % SDIM;
    int a  = cell / SSP;

    // ── RT2 (owners only; block-uniform branch): 85 scattered pred loads ──
    float l = 0.0f;
    if (owner) {
        size_t base = ((size_t)b * (AA * CH) + (size_t)a * CH) * SSP
                      + (size_t)gj * SDIM + gi;
        if (tid < NC) {
            l = preds[base + (size_t)(5 + tid) * SSP];
        } else if (tid >= 96 && tid < 101) {
            s_pred[tid - 96] = preds[base + (size_t)(tid - 96) * SSP];
        }
    }

    float cs = 0.0f;
    if (owner && tid < NC) {
        float tgt = (float)((s_bits[tid >> 5] >> (tid & 31)) & 1u);
        cs = softplusf(l) - l * tgt;
    }

    #pragma unroll
    for (int o = 16; o > 0; o >>= 1) {
        s  += __shfl_down_sync(0xffffffffu, s,  o);
        cs += __shfl_down_sync(0xffffffffu, cs, o);
    }
    if (lane == 0) { red_conf[w] = s; red_cls[w] = cs; }
    __syncthreads();                       // barrier 2

    if (tid == 0) {
        float conf_sum = red_conf[0] + red_conf[1] + red_conf[2] + red_conf[3];
        float nobj = s_nobj[0] + s_nobj[1] + s_nobj[2] + s_nobj[3];
        float dn_obj   = fmaxf(nobj, 1.0f);
        float dn_noobj = fmaxf((float)CELLS - nobj, 1.0f);
        float dn_cls   = fmaxf(nobj * (float)NC, 1.0f);

        float c = 0.5f * conf_sum / dn_noobj;
        if (blk == 0) c += 1.0f;           // constant term of loss_ciou

        if (owner) {
            float cls_sum = red_cls[0] + red_cls[1] + red_cls[2] + red_cls[3];

            float4 tbx = s_tbx;
            float cx = tbx.x * IMG, cy = tbx.y * IMG;
            float tw = tbx.z * IMG, th = tbx.w * IMG;

            float pcx = (sigmoidf(s_pred[0]) + (float)gi) * STRIDEF;
            float pcy = (sigmoidf(s_pred[1]) + (float)gj) * STRIDEF;
            float pw = anch[2 * a]     * __expf(s_pred[2]);
            float ph = anch[2 * a + 1] * __expf(s_pred[3]);
            float pc = s_pred[4];

            float ciou = ciou_f(pcx - 0.5f * pw, pcy - 0.5f * ph,
                                pcx + 0.5f * pw, pcy + 0.5f * ph,
                                cx - 0.5f * tw, cy - 0.5f * th,
                                cx + 0.5f * tw, cy + 0.5f * th);
            float sp  = softplusf(pc);
            float bce = sp - pc;

            c += (bce - ciou) / dn_obj
               + cls_sum / dn_cls
               - 0.5f * sp / dn_noobj;
        }
        atomicAdd(out, c);
    }
}

extern "C" void kernel_launch(void* const* d_in, const int* in_sizes, int n_in,
                              void* d_out, int out_size)
{
    const float* preds   = (const float*)d_in[0];
    const float* anchors = (const float*)d_in[1];
    const int*   tcls    = (const int*)d_in[2];
    const float* tbox    = (const float*)d_in[3];

    cudaMemsetAsync(d_out, 0, sizeof(float));
    yolo_one<<<NTARG, NTHR>>>(preds, anchors, tcls, tbox, (float*)d_out);
}